// round 16
// baseline (speedup 1.0000x reference)
#include <cuda_runtime.h>
#include <math.h>
#include <stdint.h>

#define DIM   4096
#define NH    32
#define HD    128
#define SEQ   4096
#define BATCH 16

typedef unsigned long long u64;

// Scratch (allocation-free)
__device__ float g_q  [BATCH * DIM];
__device__ float g_kn [BATCH * DIM];
__device__ float g_vn [BATCH * DIM];
__device__ float g_att[BATCH * DIM];

// ---------------- packed fp32x2 helpers ----------------
__device__ __forceinline__ u64 ffma2(u64 a, u64 b, u64 c) {
    u64 d; asm("fma.rn.f32x2 %0, %1, %2, %3;" : "=l"(d) : "l"(a), "l"(b), "l"(c)); return d;
}
__device__ __forceinline__ void unpack2(u64 v, float& lo, float& hi) {
    asm("mov.b64 {%0, %1}, %2;" : "=f"(lo), "=f"(hi) : "l"(v));
}
__device__ __forceinline__ void cp_async16(uint32_t dst, const void* src) {
    asm volatile("cp.async.cg.shared.global [%0], [%1], 16;" :: "r"(dst), "l"(src));
}

#define KCH    128         // k floats per stage
#define STAGES 4
#define BROWS  16          // W rows per block
#define SROWS  24          // 16 W rows + 8 x rows per stage
#define STAGE_BYTES (SROWS * KCH * 4)   // 12288

// ---------------------------------------------------------------------------
// Skinny GEMM, full cp.async block pipeline with strength-reduced addressing.
// Block: 128 threads = 4 warps; 16 W rows x 8 batches. Warp: 4 rows x 8 b.
// One unified stage buffer sbuf[4][24*128] (W rows 0-15, x rows 16-23):
// 48KB static smem. Per-thread cp.async src pointers and smem dst bases are
// computed ONCE; the per-iteration fill is ptr+=128 / dst+soff only.
// Commit EVERY iteration (incl. empty tail) -> wait_group 2 at iter kb
// guarantees stage kb has landed.
// ---------------------------------------------------------------------------
__device__ __forceinline__ void gemm_block(const float* __restrict__ x,
                                           const float* __restrict__ Wblk, // 16 rows
                                           float* __restrict__ out,
                                           int j0, int bg /* 0 or 8 */) {
    __shared__ float sbuf[STAGES][SROWS * KCH];   // 48 KB

    int tid  = threadIdx.x;
    int w    = tid >> 5;
    int lane = tid & 31;
    int rg   = w * 4;                          // warp's 4 W rows

    u64 acc[4][8];
#pragma unroll
    for (int r = 0; r < 4; r++)
#pragma unroll
        for (int b = 0; b < 8; b++) acc[r][b] = 0ull;

    // one-time setup: 6 chunks per thread (768 x 16B per stage)
    const float* src[6];
    uint32_t     dstb[6];
#pragma unroll
    for (int i = 0; i < 6; i++) {
        int c  = tid + i * 128;
        int rr = c >> 5;            // 0..23 (0-15 W, 16-23 x)
        int kc = c & 31;
        const float* g = (rr < BROWS)
            ? (Wblk + (size_t)rr * DIM)
            : (x + (size_t)(bg + rr - BROWS) * DIM);
        src[i]  = g + kc * 4;
        dstb[i] = (uint32_t)__cvta_generic_to_shared(&sbuf[0][rr * KCH + kc * 4]);
    }

    auto fill = [&](uint32_t soff) {
#pragma unroll
        for (int i = 0; i < 6; i++) {
            cp_async16(dstb[i] + soff, src[i]);
            src[i] += KCH;
        }
    };

    // prologue: 3 stages in flight
    fill(0 * STAGE_BYTES); asm volatile("cp.async.commit_group;");
    fill(1 * STAGE_BYTES); asm volatile("cp.async.commit_group;");
    fill(2 * STAGE_BYTES); asm volatile("cp.async.commit_group;");

#pragma unroll 1
    for (int kb = 0; kb < DIM / KCH; kb++) {
        asm volatile("cp.async.wait_group 2;");
        __syncthreads();

        const float* sp = sbuf[kb & (STAGES - 1)];

        ulonglong2 wv[4];
#pragma unroll
        for (int r = 0; r < 4; r++)
            wv[r] = *reinterpret_cast<const ulonglong2*>(sp + (rg + r) * KCH + lane * 4);

#pragma unroll
        for (int b = 0; b < 8; b++) {
            ulonglong2 xv = *reinterpret_cast<const ulonglong2*>(
                sp + (BROWS + b) * KCH + lane * 4);
#pragma unroll
            for (int r = 0; r < 4; r++) {
                acc[r][b] = ffma2(wv[r].x, xv.x, acc[r][b]);
                acc[r][b] = ffma2(wv[r].y, xv.y, acc[r][b]);
            }
        }

        // refill slot 3 ahead; ALWAYS commit (uniform wait_group accounting)
        if (kb + 3 < DIM / KCH) fill(((kb + 3) & (STAGES - 1)) * STAGE_BYTES);
        asm volatile("cp.async.commit_group;");
    }

    // collapse k-pairs, butterfly over lanes, lane0 writes
#pragma unroll
    for (int r = 0; r < 4; r++)
#pragma unroll
        for (int b = 0; b < 8; b++) {
            float lo, hi;
            unpack2(acc[r][b], lo, hi);
            float v = lo + hi;
#pragma unroll
            for (int off = 16; off; off >>= 1)
                v += __shfl_xor_sync(0xffffffffu, v, off);
            if (lane == 0)
                out[(size_t)(bg + b) * DIM + j0 + rg + r] = v;
        }
}

// QKV: 1536 blocks x 128 threads. blockIdx: row-block (16 rows) x batch-half.
__global__ void __launch_bounds__(128, 4) qkv_gemm(const float* __restrict__ x,
                                                   const float* __restrict__ wq,
                                                   const float* __restrict__ wk,
                                                   const float* __restrict__ wv) {
    int jg    = (blockIdx.x >> 1) * BROWS;    // fused row base
    int bg    = (blockIdx.x & 1) * 8;
    int which = jg >> 12;
    int jl    = jg & (DIM - 1);
    const float* W   = (which == 0) ? wq  : (which == 1) ? wk   : wv;
    float*       out = (which == 0) ? g_q : (which == 1) ? g_kn : g_vn;
    gemm_block(x, W + (size_t)jl * DIM, out, jl, bg);
}

// O projection: 512 blocks x 128 threads.
__global__ void __launch_bounds__(128, 4) oproj_gemm(const float* __restrict__ wo,
                                                     float* __restrict__ out) {
    int j  = (blockIdx.x >> 1) * BROWS;
    int bg = (blockIdx.x & 1) * 8;
    gemm_block(g_att, wo + (size_t)j * DIM, out, j, bg);
}

// ---------------------------------------------------------------------------
// Decode attention: one block per (b,h), 8 warps, 4-row unroll with a
// one-iteration register double-buffer: loads for iter i+1 are issued before
// the compute of iter i, giving each load a full iteration to land.
// ---------------------------------------------------------------------------
__global__ void __launch_bounds__(256, 2) decode_attn(const float* __restrict__ kc,
                                                      const float* __restrict__ vc) {
    int bh   = blockIdx.x;
    int b    = bh >> 5;
    int h    = bh & 31;
    int tid  = threadIdx.x;
    int w    = tid >> 5;
    int lane = tid & 31;

    const float4* K = reinterpret_cast<const float4*>(kc + (size_t)bh * SEQ * HD) + lane;
    const float4* V = reinterpret_cast<const float4*>(vc + (size_t)bh * SEQ * HD) + lane;

    float4 q4 = reinterpret_cast<const float4*>(g_q + b * DIM + h * HD)[lane];
    const float scale = 0.08838834764831845f;   // 1/sqrt(128)

    float  m = -INFINITY;
    float  l = 0.f;
    float4 o = make_float4(0.f, 0.f, 0.f, 0.f);

    // preload iteration 0 (rows w, w+8, w+16, w+24)
    float4 ck0 = __ldcs(K + (size_t)(w     ) * 32);
    float4 ck1 = __ldcs(K + (size_t)(w +  8) * 32);
    float4 ck2 = __ldcs(K + (size_t)(w + 16) * 32);
    float4 ck3 = __ldcs(K + (size_t)(w + 24) * 32);
    float4 cv0 = __ldcs(V + (size_t)(w     ) * 32);
    float4 cv1 = __ldcs(V + (size_t)(w +  8) * 32);
    float4 cv2 = __ldcs(V + (size_t)(w + 16) * 32);
    float4 cv3 = __ldcs(V + (size_t)(w + 24) * 32);

#pragma unroll 1
    for (int i = 0; i < SEQ / 32; i++) {
        // issue next iteration's loads first
        float4 nk0, nk1, nk2, nk3, nv0, nv1, nv2, nv3;
        if (i + 1 < SEQ / 32) {
            int rn = (i + 1) * 32 + w;
            nk0 = __ldcs(K + (size_t)(rn     ) * 32);
            nk1 = __ldcs(K + (size_t)(rn +  8) * 32);
            nk2 = __ldcs(K + (size_t)(rn + 16) * 32);
            nk3 = __ldcs(K + (size_t)(rn + 24) * 32);
            nv0 = __ldcs(V + (size_t)(rn     ) * 32);
            nv1 = __ldcs(V + (size_t)(rn +  8) * 32);
            nv2 = __ldcs(V + (size_t)(rn + 16) * 32);
            nv3 = __ldcs(V + (size_t)(rn + 24) * 32);
        }

        float s0 = q4.x * ck0.x + q4.y * ck0.y + q4.z * ck0.z + q4.w * ck0.w;
        float s1 = q4.x * ck1.x + q4.y * ck1.y + q4.z * ck1.z + q4.w * ck1.w;
        float s2 = q4.x * ck2.x + q4.y * ck2.y + q4.z * ck2.z + q4.w * ck2.w;
        float s3 = q4.x * ck3.x + q4.y * ck3.y + q4.z * ck3.z + q4.w * ck3.w;
#pragma unroll
        for (int off = 16; off; off >>= 1) {
            s0 += __shfl_xor_sync(0xffffffffu, s0, off);
            s1 += __shfl_xor_sync(0xffffffffu, s1, off);
            s2 += __shfl_xor_sync(0xffffffffu, s2, off);
            s3 += __shfl_xor_sync(0xffffffffu, s3, off);
        }
        s0 *= scale; s1 *= scale; s2 *= scale; s3 *= scale;

        float nm = fmaxf(fmaxf(m, fmaxf(s0, s1)), fmaxf(s2, s3));
        float c  = __expf(m - nm);
        float p0 = __expf(s0 - nm);
        float p1 = __expf(s1 - nm);
        float p2 = __expf(s2 - nm);
        float p3 = __expf(s3 - nm);
        l   = l * c + p0 + p1 + p2 + p3;
        o.x = o.x * c + p0 * cv0.x + p1 * cv1.x + p2 * cv2.x + p3 * cv3.x;
        o.y = o.y * c + p0 * cv0.y + p1 * cv1.y + p2 * cv2.y + p3 * cv3.y;
        o.z = o.z * c + p0 * cv0.z + p1 * cv1.z + p2 * cv2.z + p3 * cv3.z;
        o.w = o.w * c + p0 * cv0.w + p1 * cv1.w + p2 * cv2.w + p3 * cv3.w;
        m   = nm;

        ck0 = nk0; ck1 = nk1; ck2 = nk2; ck3 = nk3;
        cv0 = nv0; cv1 = nv1; cv2 = nv2; cv3 = nv3;
    }

    // new token (row 4096) handled by warp 0
    if (w == 0) {
        const float4* Kn = reinterpret_cast<const float4*>(g_kn + b * DIM + h * HD);
        const float4* Vn = reinterpret_cast<const float4*>(g_vn + b * DIM + h * HD);
        float4 kv = Kn[lane];
        float4 vv = Vn[lane];
        float s = q4.x * kv.x + q4.y * kv.y + q4.z * kv.z + q4.w * kv.w;
#pragma unroll
        for (int off = 16; off; off >>= 1)
            s += __shfl_xor_sync(0xffffffffu, s, off);
        s *= scale;
        float nm = fmaxf(m, s);
        float c  = __expf(m - nm);
        float p  = __expf(s - nm);
        l   = l * c + p;
        o.x = o.x * c + p * vv.x;
        o.y = o.y * c + p * vv.y;
        o.z = o.z * c + p * vv.z;
        o.w = o.w * c + p * vv.w;
        m   = nm;
    }

    // merge 8 warp-partials
    __shared__ float  sm[8];
    __shared__ float  sl[8];
    __shared__ float4 so[8][32];
    so[w][lane] = o;
    if (lane == 0) { sm[w] = m; sl[w] = l; }
    __syncthreads();

    if (tid < HD) {
        int d = tid;
        float gm = sm[0];
#pragma unroll
        for (int i = 1; i < 8; i++) gm = fmaxf(gm, sm[i]);
        const float* sof = reinterpret_cast<const float*>(so);
        float num = 0.f, den = 0.f;
#pragma unroll
        for (int i = 0; i < 8; i++) {
            float f = __expf(sm[i] - gm);
            num += f * sof[i * HD + d];
            den += f * sl[i];
        }
        g_att[b * DIM + h * HD + d] = num / den;
    }
}

// ---------------------------------------------------------------------------
extern "C" void kernel_launch(void* const* d_in, const int* in_sizes, int n_in,
                              void* d_out, int out_size) {
    const float* x  = (const float*)d_in[0];
    const float* kc = (const float*)d_in[1];
    const float* vc = (const float*)d_in[2];
    const float* wq = (const float*)d_in[3];
    const float* wk = (const float*)d_in[4];
    const float* wv = (const float*)d_in[5];
    const float* wo = (const float*)d_in[6];
    float* out = (float*)d_out;

    qkv_gemm  <<<(3 * DIM / BROWS) * 2, 128>>>(x, wq, wk, wv);
    decode_attn<<<BATCH * NH, 256>>>(kc, vc);
    oproj_gemm<<<(DIM / BROWS) * 2, 128>>>(wo, out);
}

// round 17
// speedup vs baseline: 1.0002x; 1.0002x over previous
#include <cuda_runtime.h>
#include <math.h>
#include <stdint.h>

#define DIM   4096
#define NH    32
#define HD    128
#define SEQ   4096
#define BATCH 16

typedef unsigned long long u64;

// Scratch (allocation-free)
__device__ float g_q  [BATCH * DIM];
__device__ float g_kn [BATCH * DIM];
__device__ float g_vn [BATCH * DIM];
__device__ float g_att[BATCH * DIM];

// ---------------- packed fp32x2 helpers ----------------
__device__ __forceinline__ u64 ffma2(u64 a, u64 b, u64 c) {
    u64 d; asm("fma.rn.f32x2 %0, %1, %2, %3;" : "=l"(d) : "l"(a), "l"(b), "l"(c)); return d;
}
__device__ __forceinline__ void unpack2(u64 v, float& lo, float& hi) {
    asm("mov.b64 {%0, %1}, %2;" : "=f"(lo), "=f"(hi) : "l"(v));
}
__device__ __forceinline__ void cp_async16(uint32_t dst, const void* src) {
    asm volatile("cp.async.cg.shared.global [%0], [%1], 16;" :: "r"(dst), "l"(src));
}

#define KCH    128         // k floats per stage
#define STAGES 4
#define BROWS  16          // W rows per block
#define SROWS  24          // 16 W rows + 8 x rows per stage
#define STAGE_BYTES (SROWS * KCH * 4)   // 12288

// ---------------------------------------------------------------------------
// Skinny GEMM, full cp.async block pipeline with strength-reduced addressing.
// Block: 128 threads = 4 warps; 16 W rows x 8 batches. Warp: 4 rows x 8 b.
// One unified stage buffer sbuf[4][24*128] (W rows 0-15, x rows 16-23):
// 48KB static smem. Per-thread cp.async src pointers and smem dst bases are
// computed ONCE; the per-iteration fill is ptr+=128 / dst+soff only.
// Commit EVERY iteration (incl. empty tail) -> wait_group 2 at iter kb
// guarantees stage kb has landed.
// ---------------------------------------------------------------------------
__device__ __forceinline__ void gemm_block(const float* __restrict__ x,
                                           const float* __restrict__ Wblk, // 16 rows
                                           float* __restrict__ out,
                                           int j0, int bg /* 0 or 8 */) {
    __shared__ float sbuf[STAGES][SROWS * KCH];   // 48 KB

    int tid  = threadIdx.x;
    int w    = tid >> 5;
    int lane = tid & 31;
    int rg   = w * 4;                          // warp's 4 W rows

    u64 acc[4][8];
#pragma unroll
    for (int r = 0; r < 4; r++)
#pragma unroll
        for (int b = 0; b < 8; b++) acc[r][b] = 0ull;

    // one-time setup: 6 chunks per thread (768 x 16B per stage)
    const float* src[6];
    uint32_t     dstb[6];
#pragma unroll
    for (int i = 0; i < 6; i++) {
        int c  = tid + i * 128;
        int rr = c >> 5;            // 0..23 (0-15 W, 16-23 x)
        int kc = c & 31;
        const float* g = (rr < BROWS)
            ? (Wblk + (size_t)rr * DIM)
            : (x + (size_t)(bg + rr - BROWS) * DIM);
        src[i]  = g + kc * 4;
        dstb[i] = (uint32_t)__cvta_generic_to_shared(&sbuf[0][rr * KCH + kc * 4]);
    }

    auto fill = [&](uint32_t soff) {
#pragma unroll
        for (int i = 0; i < 6; i++) {
            cp_async16(dstb[i] + soff, src[i]);
            src[i] += KCH;
        }
    };

    // prologue: 3 stages in flight
    fill(0 * STAGE_BYTES); asm volatile("cp.async.commit_group;");
    fill(1 * STAGE_BYTES); asm volatile("cp.async.commit_group;");
    fill(2 * STAGE_BYTES); asm volatile("cp.async.commit_group;");

#pragma unroll 1
    for (int kb = 0; kb < DIM / KCH; kb++) {
        asm volatile("cp.async.wait_group 2;");
        __syncthreads();

        const float* sp = sbuf[kb & (STAGES - 1)];

        ulonglong2 wv[4];
#pragma unroll
        for (int r = 0; r < 4; r++)
            wv[r] = *reinterpret_cast<const ulonglong2*>(sp + (rg + r) * KCH + lane * 4);

#pragma unroll
        for (int b = 0; b < 8; b++) {
            ulonglong2 xv = *reinterpret_cast<const ulonglong2*>(
                sp + (BROWS + b) * KCH + lane * 4);
#pragma unroll
            for (int r = 0; r < 4; r++) {
                acc[r][b] = ffma2(wv[r].x, xv.x, acc[r][b]);
                acc[r][b] = ffma2(wv[r].y, xv.y, acc[r][b]);
            }
        }

        // refill slot 3 ahead; ALWAYS commit (uniform wait_group accounting)
        if (kb + 3 < DIM / KCH) fill(((kb + 3) & (STAGES - 1)) * STAGE_BYTES);
        asm volatile("cp.async.commit_group;");
    }

    // collapse k-pairs, butterfly over lanes, lane0 writes
#pragma unroll
    for (int r = 0; r < 4; r++)
#pragma unroll
        for (int b = 0; b < 8; b++) {
            float lo, hi;
            unpack2(acc[r][b], lo, hi);
            float v = lo + hi;
#pragma unroll
            for (int off = 16; off; off >>= 1)
                v += __shfl_xor_sync(0xffffffffu, v, off);
            if (lane == 0)
                out[(size_t)(bg + b) * DIM + j0 + rg + r] = v;
        }
}

// QKV: 1536 blocks x 128 threads. blockIdx: row-block (16 rows) x batch-half.
__global__ void __launch_bounds__(128, 4) qkv_gemm(const float* __restrict__ x,
                                                   const float* __restrict__ wq,
                                                   const float* __restrict__ wk,
                                                   const float* __restrict__ wv) {
    int jg    = (blockIdx.x >> 1) * BROWS;    // fused row base
    int bg    = (blockIdx.x & 1) * 8;
    int which = jg >> 12;
    int jl    = jg & (DIM - 1);
    const float* W   = (which == 0) ? wq  : (which == 1) ? wk   : wv;
    float*       out = (which == 0) ? g_q : (which == 1) ? g_kn : g_vn;
    gemm_block(x, W + (size_t)jl * DIM, out, jl, bg);
}

// O projection: 512 blocks x 128 threads.
__global__ void __launch_bounds__(128, 4) oproj_gemm(const float* __restrict__ wo,
                                                     float* __restrict__ out) {
    int j  = (blockIdx.x >> 1) * BROWS;
    int bg = (blockIdx.x & 1) * 8;
    gemm_block(g_att, wo + (size_t)j * DIM, out, j, bg);
}

// ---------------------------------------------------------------------------
// Decode attention: one block per (b,h), 8 warps, 4-row unroll with a
// one-iteration register double-buffer: loads for iter i+1 are issued before
// the compute of iter i, giving each load a full iteration to land.
// ---------------------------------------------------------------------------
__global__ void __launch_bounds__(256, 2) decode_attn(const float* __restrict__ kc,
                                                      const float* __restrict__ vc) {
    int bh   = blockIdx.x;
    int b    = bh >> 5;
    int h    = bh & 31;
    int tid  = threadIdx.x;
    int w    = tid >> 5;
    int lane = tid & 31;

    const float4* K = reinterpret_cast<const float4*>(kc + (size_t)bh * SEQ * HD) + lane;
    const float4* V = reinterpret_cast<const float4*>(vc + (size_t)bh * SEQ * HD) + lane;

    float4 q4 = reinterpret_cast<const float4*>(g_q + b * DIM + h * HD)[lane];
    const float scale = 0.08838834764831845f;   // 1/sqrt(128)

    float  m = -INFINITY;
    float  l = 0.f;
    float4 o = make_float4(0.f, 0.f, 0.f, 0.f);

    // preload iteration 0 (rows w, w+8, w+16, w+24)
    float4 ck0 = __ldcs(K + (size_t)(w     ) * 32);
    float4 ck1 = __ldcs(K + (size_t)(w +  8) * 32);
    float4 ck2 = __ldcs(K + (size_t)(w + 16) * 32);
    float4 ck3 = __ldcs(K + (size_t)(w + 24) * 32);
    float4 cv0 = __ldcs(V + (size_t)(w     ) * 32);
    float4 cv1 = __ldcs(V + (size_t)(w +  8) * 32);
    float4 cv2 = __ldcs(V + (size_t)(w + 16) * 32);
    float4 cv3 = __ldcs(V + (size_t)(w + 24) * 32);

#pragma unroll 1
    for (int i = 0; i < SEQ / 32; i++) {
        // issue next iteration's loads first
        float4 nk0, nk1, nk2, nk3, nv0, nv1, nv2, nv3;
        if (i + 1 < SEQ / 32) {
            int rn = (i + 1) * 32 + w;
            nk0 = __ldcs(K + (size_t)(rn     ) * 32);
            nk1 = __ldcs(K + (size_t)(rn +  8) * 32);
            nk2 = __ldcs(K + (size_t)(rn + 16) * 32);
            nk3 = __ldcs(K + (size_t)(rn + 24) * 32);
            nv0 = __ldcs(V + (size_t)(rn     ) * 32);
            nv1 = __ldcs(V + (size_t)(rn +  8) * 32);
            nv2 = __ldcs(V + (size_t)(rn + 16) * 32);
            nv3 = __ldcs(V + (size_t)(rn + 24) * 32);
        }

        float s0 = q4.x * ck0.x + q4.y * ck0.y + q4.z * ck0.z + q4.w * ck0.w;
        float s1 = q4.x * ck1.x + q4.y * ck1.y + q4.z * ck1.z + q4.w * ck1.w;
        float s2 = q4.x * ck2.x + q4.y * ck2.y + q4.z * ck2.z + q4.w * ck2.w;
        float s3 = q4.x * ck3.x + q4.y * ck3.y + q4.z * ck3.z + q4.w * ck3.w;
#pragma unroll
        for (int off = 16; off; off >>= 1) {
            s0 += __shfl_xor_sync(0xffffffffu, s0, off);
            s1 += __shfl_xor_sync(0xffffffffu, s1, off);
            s2 += __shfl_xor_sync(0xffffffffu, s2, off);
            s3 += __shfl_xor_sync(0xffffffffu, s3, off);
        }
        s0 *= scale; s1 *= scale; s2 *= scale; s3 *= scale;

        float nm = fmaxf(fmaxf(m, fmaxf(s0, s1)), fmaxf(s2, s3));
        float c  = __expf(m - nm);
        float p0 = __expf(s0 - nm);
        float p1 = __expf(s1 - nm);
        float p2 = __expf(s2 - nm);
        float p3 = __expf(s3 - nm);
        l   = l * c + p0 + p1 + p2 + p3;
        o.x = o.x * c + p0 * cv0.x + p1 * cv1.x + p2 * cv2.x + p3 * cv3.x;
        o.y = o.y * c + p0 * cv0.y + p1 * cv1.y + p2 * cv2.y + p3 * cv3.y;
        o.z = o.z * c + p0 * cv0.z + p1 * cv1.z + p2 * cv2.z + p3 * cv3.z;
        o.w = o.w * c + p0 * cv0.w + p1 * cv1.w + p2 * cv2.w + p3 * cv3.w;
        m   = nm;

        ck0 = nk0; ck1 = nk1; ck2 = nk2; ck3 = nk3;
        cv0 = nv0; cv1 = nv1; cv2 = nv2; cv3 = nv3;
    }

    // new token (row 4096) handled by warp 0
    if (w == 0) {
        const float4* Kn = reinterpret_cast<const float4*>(g_kn + b * DIM + h * HD);
        const float4* Vn = reinterpret_cast<const float4*>(g_vn + b * DIM + h * HD);
        float4 kv = Kn[lane];
        float4 vv = Vn[lane];
        float s = q4.x * kv.x + q4.y * kv.y + q4.z * kv.z + q4.w * kv.w;
#pragma unroll
        for (int off = 16; off; off >>= 1)
            s += __shfl_xor_sync(0xffffffffu, s, off);
        s *= scale;
        float nm = fmaxf(m, s);
        float c  = __expf(m - nm);
        float p  = __expf(s - nm);
        l   = l * c + p;
        o.x = o.x * c + p * vv.x;
        o.y = o.y * c + p * vv.y;
        o.z = o.z * c + p * vv.z;
        o.w = o.w * c + p * vv.w;
        m   = nm;
    }

    // merge 8 warp-partials
    __shared__ float  sm[8];
    __shared__ float  sl[8];
    __shared__ float4 so[8][32];
    so[w][lane] = o;
    if (lane == 0) { sm[w] = m; sl[w] = l; }
    __syncthreads();

    if (tid < HD) {
        int d = tid;
        float gm = sm[0];
#pragma unroll
        for (int i = 1; i < 8; i++) gm = fmaxf(gm, sm[i]);
        const float* sof = reinterpret_cast<const float*>(so);
        float num = 0.f, den = 0.f;
#pragma unroll
        for (int i = 0; i < 8; i++) {
            float f = __expf(sm[i] - gm);
            num += f * sof[i * HD + d];
            den += f * sl[i];
        }
        g_att[b * DIM + h * HD + d] = num / den;
    }
}

// ---------------------------------------------------------------------------
extern "C" void kernel_launch(void* const* d_in, const int* in_sizes, int n_in,
                              void* d_out, int out_size) {
    const float* x  = (const float*)d_in[0];
    const float* kc = (const float*)d_in[1];
    const float* vc = (const float*)d_in[2];
    const float* wq = (const float*)d_in[3];
    const float* wk = (const float*)d_in[4];
    const float* wv = (const float*)d_in[5];
    const float* wo = (const float*)d_in[6];
    float* out = (float*)d_out;

    qkv_gemm  <<<(3 * DIM / BROWS) * 2, 128>>>(x, wq, wk, wv);
    decode_attn<<<BATCH * NH, 256>>>(kc, vc);
    oproj_gemm<<<(DIM / BROWS) * 2, 128>>>(wo, out);
}